// round 14
// baseline (speedup 1.0000x reference)
#include <cuda_runtime.h>

#define E_DIM 8
#define F_DIM 32
#define TPT 4          // tokens per thread: amortize constant-port traffic
#define THREADS 128

using u64 = unsigned long long;

// Parameter blob in the constant bank; prep kernel writes the backing store
// directly (validated R9/R10: rel_err identical, no memcpy node needed).
struct __align__(16) CBlob {
    float w1[E_DIM * F_DIM];   // [E][F] row-major
    float w2[F_DIM * E_DIM];   // [F][E] row-major
    float b1[F_DIM];
    float b2[E_DIM];
    float th[E_DIM];
    float pad[4];
};

__constant__ CBlob c_blob;

__global__ void prep_kernel(float* __restrict__ dst_blob,   // = &c_blob backing
                            const float* __restrict__ theta,
                            const float* __restrict__ w1,
                            const float* __restrict__ b1,
                            const float* __restrict__ w2,
                            const float* __restrict__ b2)
{
    CBlob* b = (CBlob*)dst_blob;
    const int t = threadIdx.x;                      // 128 threads, 2 each
    b->w1[t]       = w1[t];
    b->w1[t + 128] = w1[t + 128];
    b->w2[t]       = w2[t];
    b->w2[t + 128] = w2[t + 128];
    if (t < F_DIM)                    b->b1[t] = b1[t];
    else if (t < F_DIM + E_DIM)       b->b2[t - F_DIM] = b2[t - F_DIM];
    else if (t < F_DIM + 2 * E_DIM)   b->th[t - F_DIM - E_DIM] =
                                          theta[t - F_DIM - E_DIM];
}

__device__ __forceinline__ u64 pack2(float lo, float hi) {
    u64 r;
    asm("mov.b64 %0, {%1, %2};" : "=l"(r) : "f"(lo), "f"(hi));
    return r;
}
__device__ __forceinline__ void unpack2(u64 v, float& lo, float& hi) {
    asm("mov.b64 {%0, %1}, %2;" : "=f"(lo), "=f"(hi) : "l"(v));
}
// Packed dual fp32 FMA (Blackwell f32x2 pipe).
__device__ __forceinline__ u64 fma2(u64 a, u64 b, u64 c) {
    u64 d;
    asm("fma.rn.f32x2 %0, %1, %2, %3;" : "=l"(d) : "l"(a), "l"(b), "l"(c));
    return d;
}

// min 6 blocks/SM -> reg cap 85 (currently 82): 24 resident warps/SM.
__global__ void __launch_bounds__(THREADS, 6)
ffq_kernel(const float* __restrict__ x,
           float* __restrict__ out,
           long long n_tokens)
{
    const long long token0 =
        ((long long)blockIdx.x * THREADS + threadIdx.x) * TPT;
    if (token0 + TPT - 1 >= n_tokens) return;   // exact grid in practice

    // ---- load x for 4 tokens: 128 contiguous bytes ----
    const float4* xp = (const float4*)(x + token0 * E_DIM);

    // ---- quantum layer: q = cos(x + theta), pre-packed (q,q) ----
    u64 q[TPT][E_DIM];
#pragma unroll
    for (int tok = 0; tok < TPT; tok++) {
        const float4 lo = xp[2 * tok], hi = xp[2 * tok + 1];
        float c;
        c = __cosf(lo.x + c_blob.th[0]); q[tok][0] = pack2(c, c);
        c = __cosf(lo.y + c_blob.th[1]); q[tok][1] = pack2(c, c);
        c = __cosf(lo.z + c_blob.th[2]); q[tok][2] = pack2(c, c);
        c = __cosf(lo.w + c_blob.th[3]); q[tok][3] = pack2(c, c);
        c = __cosf(hi.x + c_blob.th[4]); q[tok][4] = pack2(c, c);
        c = __cosf(hi.y + c_blob.th[5]); q[tok][5] = pack2(c, c);
        c = __cosf(hi.z + c_blob.th[6]); q[tok][6] = pack2(c, c);
        c = __cosf(hi.w + c_blob.th[7]); q[tok][7] = pack2(c, c);
    }

    // ---- output accumulators: packed E pairs per token, init with b2 ----
    u64 o[TPT][E_DIM / 2];
    {
        float4 ba = *(const float4*)&c_blob.b2[0];
        float4 bb = *(const float4*)&c_blob.b2[4];
        u64 i0 = pack2(ba.x, ba.y), i1 = pack2(ba.z, ba.w);
        u64 i2 = pack2(bb.x, bb.y), i3 = pack2(bb.z, bb.w);
#pragma unroll
        for (int tok = 0; tok < TPT; tok++) {
            o[tok][0] = i0; o[tok][1] = i1; o[tok][2] = i2; o[tok][3] = i3;
        }
    }

    // ---- fused layer1+layer2, 4 F-columns per iteration ----
#pragma unroll
    for (int f4 = 0; f4 < F_DIM / 4; f4++) {
        // layer 1: h for 4 f-values (two packed pairs) per token
        float4 bb = *(const float4*)&c_blob.b1[f4 * 4];          // LDC.128
        u64 hA[TPT], hB[TPT];
        {
            u64 bA = pack2(bb.x, bb.y), bB = pack2(bb.z, bb.w);
#pragma unroll
            for (int tok = 0; tok < TPT; tok++) { hA[tok] = bA; hB[tok] = bB; }
        }
#pragma unroll
        for (int i = 0; i < E_DIM; i++) {
            float4 w = *(const float4*)&c_blob.w1[i * F_DIM + f4 * 4];  // LDC.128
            u64 wA = pack2(w.x, w.y), wB = pack2(w.z, w.w);
#pragma unroll
            for (int tok = 0; tok < TPT; tok++) {
                hA[tok] = fma2(q[tok][i], wA, hA[tok]);
                hB[tok] = fma2(q[tok][i], wB, hB[tok]);
            }
        }

        // relu + layer 2 for these 4 f-values
        float hh[TPT][4];
#pragma unroll
        for (int tok = 0; tok < TPT; tok++) {
            unpack2(hA[tok], hh[tok][0], hh[tok][1]);
            unpack2(hB[tok], hh[tok][2], hh[tok][3]);
        }
#pragma unroll
        for (int j = 0; j < 4; j++) {
            const int f = f4 * 4 + j;
            float4 wa = *(const float4*)&c_blob.w2[f * E_DIM];       // LDC.128
            float4 wb = *(const float4*)&c_blob.w2[f * E_DIM + 4];   // LDC.128
            u64 w01 = pack2(wa.x, wa.y), w23 = pack2(wa.z, wa.w);
            u64 w45 = pack2(wb.x, wb.y), w67 = pack2(wb.z, wb.w);
#pragma unroll
            for (int tok = 0; tok < TPT; tok++) {
                float d = fmaxf(hh[tok][j], 0.0f);
                u64 p = pack2(d, d);
                o[tok][0] = fma2(p, w01, o[tok][0]);
                o[tok][1] = fma2(p, w23, o[tok][1]);
                o[tok][2] = fma2(p, w45, o[tok][2]);
                o[tok][3] = fma2(p, w67, o[tok][3]);
            }
        }
    }

    // ---- store 4 tokens: 128 contiguous bytes ----
    float4* op = (float4*)(out + token0 * E_DIM);
#pragma unroll
    for (int tok = 0; tok < TPT; tok++) {
        float4 rlo, rhi;
        unpack2(o[tok][0], rlo.x, rlo.y); unpack2(o[tok][1], rlo.z, rlo.w);
        unpack2(o[tok][2], rhi.x, rhi.y); unpack2(o[tok][3], rhi.z, rhi.w);
        op[2 * tok]     = rlo;
        op[2 * tok + 1] = rhi;
    }
}

extern "C" void kernel_launch(void* const* d_in, const int* in_sizes, int n_in,
                              void* d_out, int out_size) {
    const float* x     = (const float*)d_in[0];
    const float* theta = (const float*)d_in[1];
    const float* w1    = (const float*)d_in[2];
    const float* b1    = (const float*)d_in[3];
    const float* w2    = (const float*)d_in[4];
    const float* b2    = (const float*)d_in[5];
    float* out         = (float*)d_out;

    void* blob_dev = nullptr;
    (void)cudaGetSymbolAddress(&blob_dev, c_blob);

    // Node 1: gather inputs straight into the constant bank's backing store.
    prep_kernel<<<1, THREADS>>>((float*)blob_dev, theta, w1, b1, w2, b2);

    // Node 2: main kernel, 4 tokens/thread, 6 blocks/SM residency.
    const long long n_tokens = (long long)in_sizes[0] / E_DIM;  // B*S
    const long long quads    = n_tokens / TPT;
    const int blocks         = (int)((quads + THREADS - 1) / THREADS);
    ffq_kernel<<<blocks, THREADS>>>(x, out, n_tokens);
}

// round 15
// speedup vs baseline: 1.0581x; 1.0581x over previous
#include <cuda_runtime.h>

#define THREADS 256
#define WARPS_PER_BLOCK 8
#define TILES_PER_WARP 2
#define TILE_M 16
#define E_DIM 8
#define F_DIM 32

// f32 -> tf32 (round-to-nearest)
__device__ __forceinline__ unsigned f2tf(float f) {
    unsigned r; asm("cvt.rna.tf32.f32 %0, %1;" : "=r"(r) : "f"(f)); return r;
}
// m16n8k8 tf32 MMA, D = A*B + D
__device__ __forceinline__ void mma8(float* c, const unsigned* a, const unsigned* b) {
    asm volatile("mma.sync.aligned.m16n8k8.row.col.f32.tf32.tf32.f32 "
        "{%0,%1,%2,%3}, {%4,%5,%6,%7}, {%8,%9}, {%0,%1,%2,%3};"
        : "+f"(c[0]), "+f"(c[1]), "+f"(c[2]), "+f"(c[3])
        : "r"(a[0]), "r"(a[1]), "r"(a[2]), "r"(a[3]),
          "r"(b[0]), "r"(b[1]));
}

__global__ void __launch_bounds__(THREADS, 3)
ffq_kernel(const float* __restrict__ x, const float* __restrict__ theta,
           const float* __restrict__ w1, const float* __restrict__ b1,
           const float* __restrict__ w2, const float* __restrict__ b2,
           float* __restrict__ out, long long n_tiles)
{
    // Per-warp h buffer: 16 tokens x 32 features, XOR-8 swizzled columns.
    __shared__ float hbuf[WARPS_PER_BLOCK][TILE_M * F_DIM];   // 16 KB

    const int warp = threadIdx.x >> 5;
    const int lane = threadIdx.x & 31;
    const int g    = lane >> 2;    // groupID 0..7  (row within tile)
    const int tig  = lane & 3;     // thread-in-group 0..3

    // ---- loop-invariant fragments (loaded once per warp) ----
    // GEMM1 B = w1 [k=E=8][n=F=32]; b0: (k=tig, n=nt*8+g), b1: (k=tig+4, ...)
    unsigned w1b[4][2], w2b[4][2];
#pragma unroll
    for (int nt = 0; nt < 4; nt++) {
        w1b[nt][0] = f2tf(w1[ tig      * F_DIM + nt * 8 + g]);
        w1b[nt][1] = f2tf(w1[(tig + 4) * F_DIM + nt * 8 + g]);
    }
    // GEMM2 B = w2 [k=F=32][n=E=8]; kchunk kc: b0: (k=kc*8+tig, n=g)
#pragma unroll
    for (int kc = 0; kc < 4; kc++) {
        w2b[kc][0] = f2tf(w2[(kc * 8 + tig    ) * E_DIM + g]);
        w2b[kc][1] = f2tf(w2[(kc * 8 + tig + 4) * E_DIM + g]);
    }
    // C-fragment biases: cols 2tig, 2tig+1 (rows share columns)
    float bias1[4][2];
#pragma unroll
    for (int nt = 0; nt < 4; nt++) {
        bias1[nt][0] = b1[nt * 8 + 2 * tig];
        bias1[nt][1] = b1[nt * 8 + 2 * tig + 1];
    }
    const float bz0 = b2[2 * tig], bz1 = b2[2 * tig + 1];
    const float th0 = theta[tig], th1 = theta[tig + 4];

    const int sw = (g & 3) << 3;          // per-row-group column swizzle
    float* hw = hbuf[warp];

    long long tile = ((long long)blockIdx.x * WARPS_PER_BLOCK + warp)
                     * TILES_PER_WARP;
#pragma unroll
    for (int tt = 0; tt < TILES_PER_WARP; tt++, tile++) {
        if (tile >= n_tiles) break;
        const long long tb = tile * TILE_M;
        const float* xr = x + tb * E_DIM;

        // ---- A fragment for GEMM1: q = cos(x + theta), tf32 ----
        // a0:(row g, k tig) a1:(g+8, tig) a2:(g, tig+4) a3:(g+8, tig+4)
        unsigned a[4];
        a[0] = f2tf(__cosf(xr[ g      * E_DIM + tig    ] + th0));
        a[1] = f2tf(__cosf(xr[(g + 8) * E_DIM + tig    ] + th0));
        a[2] = f2tf(__cosf(xr[ g      * E_DIM + tig + 4] + th1));
        a[3] = f2tf(__cosf(xr[(g + 8) * E_DIM + tig + 4] + th1));

        // ---- GEMM1 (4 n-tiles) + relu -> swizzled smem ----
#pragma unroll
        for (int nt = 0; nt < 4; nt++) {
            float h[4] = {bias1[nt][0], bias1[nt][1],
                          bias1[nt][0], bias1[nt][1]};
            mma8(h, a, w1b[nt]);
            const int c0 = (nt * 8 + 2 * tig) ^ sw;
            *(float2*)&hw[ g      * F_DIM + c0] =
                make_float2(fmaxf(h[0], 0.f), fmaxf(h[1], 0.f));
            *(float2*)&hw[(g + 8) * F_DIM + c0] =
                make_float2(fmaxf(h[2], 0.f), fmaxf(h[3], 0.f));
        }
        __syncwarp();

        // ---- GEMM2: o = relu(h) @ w2 + b2, K=32 as 4 chunks ----
        float o[4] = {bz0, bz1, bz0, bz1};
#pragma unroll
        for (int kc = 0; kc < 4; kc++) {
            unsigned a2[4];
            const int cA = (kc * 8 + tig    ) ^ sw;
            const int cB = (kc * 8 + tig + 4) ^ sw;
            a2[0] = f2tf(hw[ g      * F_DIM + cA]);
            a2[1] = f2tf(hw[(g + 8) * F_DIM + cA]);
            a2[2] = f2tf(hw[ g      * F_DIM + cB]);
            a2[3] = f2tf(hw[(g + 8) * F_DIM + cB]);
            mma8(o, a2, w2b[kc]);
        }
        __syncwarp();   // loads done before next tile overwrites hw

        // ---- store: thread owns (g, 2tig..2tig+1) and (g+8, ...) ----
        float* orow = out + tb * E_DIM;
        *(float2*)&orow[ g      * E_DIM + 2 * tig] = make_float2(o[0], o[1]);
        *(float2*)&orow[(g + 8) * E_DIM + 2 * tig] = make_float2(o[2], o[3]);
    }
}

extern "C" void kernel_launch(void* const* d_in, const int* in_sizes, int n_in,
                              void* d_out, int out_size) {
    const float* x     = (const float*)d_in[0];
    const float* theta = (const float*)d_in[1];
    const float* w1    = (const float*)d_in[2];
    const float* b1    = (const float*)d_in[3];
    const float* w2    = (const float*)d_in[4];
    const float* b2    = (const float*)d_in[5];
    float* out         = (float*)d_out;

    const long long n_tokens = (long long)in_sizes[0] / E_DIM;   // B*S
    const long long n_tiles  = n_tokens / TILE_M;                // 32768
    const long long per_blk  = (long long)WARPS_PER_BLOCK * TILES_PER_WARP;
    const int blocks         = (int)((n_tiles + per_blk - 1) / per_blk);

    // Single graph node.
    ffq_kernel<<<blocks, THREADS>>>(x, theta, w1, b1, w2, b2, out, n_tiles);
}